// round 14
// baseline (speedup 1.0000x reference)
#include <cuda_runtime.h>
#include <cuda_fp16.h>
#include <math.h>
#include <stdint.h>

// Problem constants
#define BQ 2
#define LQ 2048
#define DQ 512
#define DI 1024
#define BL (BQ*LQ)          // 4096 rows
#define DSTATE 16
#define NG 8
#define TC 128              // scan chunk length
#define NCH (LQ/TC)         // 16 chunks

// ---------------- device scratch ---------------------------------------------
__device__ float g_xz[(size_t)BL*2048];      // in_proj output (xm | z), fp32
__device__ float g_xc[(size_t)BL*DI];        // conv+silu
__device__ float g_dbc[BL*64];               // x_proj output
__device__ float g_x2[BL*DQ];                // x + mix

__device__ float g_Si[(size_t)BQ*NCH*DI*DSTATE]; // inclusive chunk states
__device__ int   g_flag[BQ*NCH*64];              // chunk-ready flags

__device__ __half g_uh[(size_t)BL*DQ];           // ln2(x) fp16
__device__ __half g_iwh[2048*DQ];                // in_w fp16
__device__ __half g_yh[(size_t)BL*DI];           // scan out fp16
__device__ __half g_owh[DQ*DI];                  // out_w fp16
__device__ __half g_bh[(size_t)BL*4096];         // KAN basis fp16
__device__ __half g_swh[DQ*4096];                // spl_w fp16

// ---------------- PTX helpers -------------------------------------------------
#define CP_ASYNC16(s, g) \
    asm volatile("cp.async.cg.shared.global [%0], [%1], 16;" :: "r"(s), "l"(g))
#define CP_COMMIT() asm volatile("cp.async.commit_group;" ::: "memory")
#define CP_WAIT(n)  asm volatile("cp.async.wait_group %0;" :: "n"(n) : "memory")

__device__ __forceinline__ void ldsm4(uint32_t* r, uint32_t addr) {
    asm volatile("ldmatrix.sync.aligned.m8n8.x4.shared.b16 {%0,%1,%2,%3}, [%4];"
                 : "=r"(r[0]), "=r"(r[1]), "=r"(r[2]), "=r"(r[3]) : "r"(addr));
}
__device__ __forceinline__ void mma_f16(float* c, const uint32_t* a, const uint32_t* b) {
    asm volatile("mma.sync.aligned.m16n8k16.row.col.f32.f16.f16.f32 "
                 "{%0,%1,%2,%3}, {%4,%5,%6,%7}, {%8,%9}, {%0,%1,%2,%3};"
                 : "+f"(c[0]), "+f"(c[1]), "+f"(c[2]), "+f"(c[3])
                 : "r"(a[0]), "r"(a[1]), "r"(a[2]), "r"(a[3]),
                   "r"(b[0]), "r"(b[1]));
}

// ---------------- epilogue flags ---------------------------------------------
#define EPI_BIAS 1
#define EPI_RESID 2

// ---------------- fp16 NT GEMM via mma.sync, 3-stage pipeline -----------------
#define MG_STRIDE 80
#define MG_A 10240
#define MG_STAGE (2 * MG_A)
#define MG_SMEM (3 * MG_STAGE)     // 61440

template<int EPI>
__global__ __launch_bounds__(256, 2)
void mgemm(const __half* __restrict__ Ah, const __half* __restrict__ Bh,
           const float* __restrict__ bias, const float* __restrict__ resid,
           float* __restrict__ C, int N, int K) {
    extern __shared__ __align__(128) char smem[];
    uint32_t sb = (uint32_t)__cvta_generic_to_shared(smem);
    int tid = threadIdx.x;
    int lane = tid & 31, warp = tid >> 5;
    int bm = blockIdx.y * 128, bn = blockIdx.x * 128;
    int wm = (warp >> 2) * 64;
    int wn = (warp & 3) * 32;

    int nc = K / 32;

    auto issue = [&](int c) {
        int k0 = c * 32;
        uint32_t bufb = sb + (uint32_t)(c % 3) * MG_STAGE;
        #pragma unroll
        for (int i = 0; i < 2; i++) {
            int idx = tid + i * 256;
            int row = idx >> 2, seg = idx & 3;
            CP_ASYNC16(bufb + row * MG_STRIDE + seg * 16,
                       Ah + (size_t)(bm + row) * K + k0 + seg * 8);
        }
        #pragma unroll
        for (int i = 0; i < 2; i++) {
            int idx = tid + i * 256;
            int row = idx >> 2, seg = idx & 3;
            CP_ASYNC16(bufb + MG_A + row * MG_STRIDE + seg * 16,
                       Bh + (size_t)(bn + row) * K + k0 + seg * 8);
        }
        CP_COMMIT();
    };

    float acc[4][4][4];
    #pragma unroll
    for (int mt = 0; mt < 4; mt++)
        #pragma unroll
        for (int nt = 0; nt < 4; nt++)
            #pragma unroll
            for (int q = 0; q < 4; q++) acc[mt][nt][q] = 0.f;

    issue(0); issue(1); issue(2);

    for (int c = 0; c < nc; c++) {
        int left = nc - 1 - c;
        if (left >= 2)      { CP_WAIT(2); }
        else if (left == 1) { CP_WAIT(1); }
        else                { CP_WAIT(0); }
        __syncthreads();
        uint32_t base = sb + (uint32_t)(c % 3) * MG_STAGE;
        uint32_t rsel = (lane & 15) * MG_STRIDE;
        #pragma unroll
        for (int kst = 0; kst < 2; kst++) {
            uint32_t kb = kst * 32 + (lane >> 4) * 16;
            uint32_t bf[4][2], af[4][4];
            #pragma unroll
            for (int p = 0; p < 2; p++) {
                uint32_t r[4];
                ldsm4(r, base + MG_A + (wn + p * 16) * MG_STRIDE + rsel + kb);
                bf[p*2][0] = r[0]; bf[p*2][1] = r[2];
                bf[p*2+1][0] = r[1]; bf[p*2+1][1] = r[3];
            }
            #pragma unroll
            for (int mt = 0; mt < 4; mt++)
                ldsm4(af[mt], base + (wm + mt * 16) * MG_STRIDE + rsel + kb);
            #pragma unroll
            for (int mt = 0; mt < 4; mt++)
                #pragma unroll
                for (int nt = 0; nt < 4; nt++)
                    mma_f16(acc[mt][nt], af[mt], bf[nt]);
        }
        __syncthreads();
        if (c + 3 < nc) issue(c + 3);
    }

    int g = lane >> 2, tig = lane & 3;
    #pragma unroll
    for (int mt = 0; mt < 4; mt++) {
        size_t r0 = (size_t)bm + wm + mt * 16 + g;
        size_t r1 = r0 + 8;
        #pragma unroll
        for (int nt = 0; nt < 4; nt++) {
            int col = bn + wn + nt * 8 + tig * 2;
            float2 v0 = make_float2(acc[mt][nt][0], acc[mt][nt][1]);
            float2 v1 = make_float2(acc[mt][nt][2], acc[mt][nt][3]);
            if (EPI & EPI_BIAS) {
                float b0 = bias[col], b1 = bias[col + 1];
                v0.x += b0; v0.y += b1; v1.x += b0; v1.y += b1;
            }
            if (EPI & EPI_RESID) {
                const float* rp0 = resid + r0 * N + col;
                const float* rp1 = resid + r1 * N + col;
                v0.x += rp0[0]; v0.y += rp0[1];
                v1.x += rp1[0]; v1.y += rp1[1];
            }
            *(float2*)(C + r0 * N + col) = v0;
            *(float2*)(C + r1 * N + col) = v1;
        }
    }
}

// ---------------- double-LN core ----------------------------------------------
__device__ __forceinline__ void ln2_core(float4 v[4], int lane,
                                         const float* __restrict__ w1,
                                         const float* __restrict__ b1,
                                         const float* __restrict__ w2,
                                         const float* __restrict__ b2) {
    #pragma unroll
    for (int pass = 0; pass < 2; pass++) {
        const float* wz = pass ? w2 : w1;
        const float* bz = pass ? b2 : b1;
        float s = 0.f;
        #pragma unroll
        for (int i = 0; i < 4; i++) s += v[i].x + v[i].y + v[i].z + v[i].w;
        #pragma unroll
        for (int o = 16; o > 0; o >>= 1) s += __shfl_xor_sync(0xffffffffu, s, o);
        float mu = s * (1.f / DQ);
        float q = 0.f;
        #pragma unroll
        for (int i = 0; i < 4; i++) {
            float a = v[i].x - mu, b = v[i].y - mu, c = v[i].z - mu, d = v[i].w - mu;
            q += a * a + b * b + c * c + d * d;
        }
        #pragma unroll
        for (int o = 16; o > 0; o >>= 1) q += __shfl_xor_sync(0xffffffffu, q, o);
        float rs = rsqrtf(q * (1.f / DQ) + 1e-5f);
        #pragma unroll
        for (int i = 0; i < 4; i++) {
            float4 w = ((const float4*)wz)[lane + i * 32];
            float4 b = ((const float4*)bz)[lane + i * 32];
            v[i].x = (v[i].x - mu) * rs * w.x + b.x;
            v[i].y = (v[i].y - mu) * rs * w.y + b.y;
            v[i].z = (v[i].z - mu) * rs * w.z + b.z;
            v[i].w = (v[i].w - mu) * rs * w.w + b.w;
        }
    }
}

// ---------------- merged: weight convert + flag clear + ln2(x) -> fp16 --------
// blocks [0, WBLK): weight conversion; blocks [WBLK, WBLK+512): ln2 rows
#define W1N (2048*DQ/4)
#define W2N (DQ*DI/4)
#define W3N (DQ*4096/4)
#define WTOT (W1N + W2N + W3N)              // 917504
#define WBLK ((WTOT + 255) / 256)           // 3584
__global__ __launch_bounds__(256)
void pre_kernel(const float* __restrict__ s1, __half* __restrict__ h1,
                const float* __restrict__ s2, __half* __restrict__ h2,
                const float* __restrict__ s3, __half* __restrict__ h3,
                int* __restrict__ flags,
                const float* __restrict__ x,
                const float* __restrict__ w1, const float* __restrict__ b1,
                const float* __restrict__ w2, const float* __restrict__ b2,
                __half* __restrict__ oh) {
    if (blockIdx.x < WBLK) {
        int i = blockIdx.x * 256 + threadIdx.x;
        if (i < BQ * NCH * 64) flags[i] = 0;
        const float* s; __half* h; int j;
        if (i < W1N)            { s = s1; h = h1; j = i; }
        else if (i < W1N + W2N) { s = s2; h = h2; j = i - W1N; }
        else if (i < WTOT)      { s = s3; h = h3; j = i - W1N - W2N; }
        else return;
        float4 v = ((const float4*)s)[j];
        __half2* hp = (__half2*)h;
        hp[2 * j + 0] = __halves2half2(__float2half_rn(v.x), __float2half_rn(v.y));
        hp[2 * j + 1] = __halves2half2(__float2half_rn(v.z), __float2half_rn(v.w));
        return;
    }
    // ln2 part
    int lane = threadIdx.x & 31;
    int row = (blockIdx.x - WBLK) * 8 + (threadIdx.x >> 5);
    const float4* xr = (const float4*)(x + (size_t)row * DQ);
    float4 v[4];
    #pragma unroll
    for (int i = 0; i < 4; i++) v[i] = xr[lane + i * 32];
    ln2_core(v, lane, w1, b1, w2, b2);
    __half2* hp = (__half2*)(oh + (size_t)row * DQ);
    #pragma unroll
    for (int i = 0; i < 4; i++) {
        int j = (lane + i * 32) * 2;
        hp[j + 0] = __halves2half2(__float2half_rn(v[i].x), __float2half_rn(v[i].y));
        hp[j + 1] = __halves2half2(__float2half_rn(v[i].z), __float2half_rn(v[i].w));
    }
}

// ---------------- fused ln2 + KAN basis via smem LUT -> fp16 -------------------
// basis(u) = sech2(u), u = |k - g| * INV. LUT over u in [0, 8], 2048 intervals,
// entry i = (f(i*h), f((i+1)*h) - f(i*h)); linear interp.
#define LUT_N 2048
#define LUT_MAX 8.0f
#define LUT_SCALE ((float)LUT_N / LUT_MAX)
__global__ __launch_bounds__(256)
void ln2_basis_kernel(const float* __restrict__ x,
                      const float* __restrict__ w1, const float* __restrict__ b1,
                      const float* __restrict__ w2, const float* __restrict__ b2,
                      const float* __restrict__ grid,
                      __half* __restrict__ bh) {
    __shared__ float2 lut[LUT_N + 1];
    const float INV = 1.0f / 0.33f;
    const float h = LUT_MAX / LUT_N;
    // build LUT
    for (int i = threadIdx.x; i <= LUT_N; i += 256) {
        float u0 = i * h, u1 = u0 + h;
        float e0 = __expf(-2.f * u0);
        float e1 = __expf(-2.f * u1);
        float f0 = 4.f * e0 / ((1.f + e0) * (1.f + e0));
        float f1 = 4.f * e1 / ((1.f + e1) * (1.f + e1));
        lut[i] = make_float2(f0, f1 - f0);
    }
    int lane = threadIdx.x & 31;
    int row = blockIdx.x * 8 + (threadIdx.x >> 5);
    const float4* xr = (const float4*)(x + (size_t)row * DQ);
    float4 v[4];
    #pragma unroll
    for (int i = 0; i < 4; i++) v[i] = xr[lane + i * 32];
    ln2_core(v, lane, w1, b1, w2, b2);

    float gg[8];
    #pragma unroll
    for (int g = 0; g < 8; g++) gg[g] = __ldg(grid + g);
    __syncthreads();

    __half* brow = bh + (size_t)row * 4096;
    #pragma unroll
    for (int i = 0; i < 4; i++) {
        float kv4[4] = {v[i].x, v[i].y, v[i].z, v[i].w};
        #pragma unroll
        for (int c = 0; c < 4; c++) {
            float kv = kv4[c];
            int d = (lane + i * 32) * 4 + c;
            __half hs[8];
            #pragma unroll
            for (int g = 0; g < 8; g++) {
                float u = fabsf((kv - gg[g]) * INV);
                float xq = fminf(u * LUT_SCALE, (float)LUT_N - 0.001f);
                int ii = (int)xq;
                float fr = xq - ii;
                float2 e = lut[ii];
                hs[g] = __float2half_rn(fmaf(fr, e.y, e.x));
            }
            *(uint4*)(brow + d * 8) = *(uint4*)hs;
        }
    }
}

// ---------------- causal conv+silu, sliding-window, seg=8 ---------------------
__global__ __launch_bounds__(256)
void conv_silu_kernel(const float* __restrict__ xz,
                      const float* __restrict__ cw,
                      const float* __restrict__ cb,
                      float* __restrict__ xc) {
    int b = blockIdx.x >> 8;
    int seg = blockIdx.x & 255;
    int d4 = threadIdx.x * 4;
    int t0 = seg * 8;
    size_t rbase = (size_t)b * LQ;

    float4 cw0 = *(const float4*)(cw + (d4 + 0) * 4);
    float4 cw1 = *(const float4*)(cw + (d4 + 1) * 4);
    float4 cw2 = *(const float4*)(cw + (d4 + 2) * 4);
    float4 cw3 = *(const float4*)(cw + (d4 + 3) * 4);
    float4 bias = *(const float4*)(cb + d4);

    float4 w0, w1, w2;
    {
        int t = t0 - 3;
        w0 = (t >= 0) ? *(const float4*)(xz + (rbase + t) * 2048 + d4)
                      : make_float4(0.f, 0.f, 0.f, 0.f);
        t = t0 - 2;
        w1 = (t >= 0) ? *(const float4*)(xz + (rbase + t) * 2048 + d4)
                      : make_float4(0.f, 0.f, 0.f, 0.f);
        t = t0 - 1;
        w2 = (t >= 0) ? *(const float4*)(xz + (rbase + t) * 2048 + d4)
                      : make_float4(0.f, 0.f, 0.f, 0.f);
    }
    #pragma unroll
    for (int tt = 0; tt < 8; tt++) {
        int t = t0 + tt;
        float4 cur = *(const float4*)(xz + (rbase + t) * 2048 + d4);
        float4 a = bias;
        a.x = fmaf(w0.x, cw0.x, fmaf(w1.x, cw0.y, fmaf(w2.x, cw0.z, fmaf(cur.x, cw0.w, a.x))));
        a.y = fmaf(w0.y, cw1.x, fmaf(w1.y, cw1.y, fmaf(w2.y, cw1.z, fmaf(cur.y, cw1.w, a.y))));
        a.z = fmaf(w0.z, cw2.x, fmaf(w1.z, cw2.y, fmaf(w2.z, cw2.z, fmaf(cur.z, cw2.w, a.z))));
        a.w = fmaf(w0.w, cw3.x, fmaf(w1.w, cw3.y, fmaf(w2.w, cw3.z, fmaf(cur.w, cw3.w, a.w))));
        a.x *= 1.f / (1.f + __expf(-a.x));
        a.y *= 1.f / (1.f + __expf(-a.y));
        a.z *= 1.f / (1.f + __expf(-a.z));
        a.w *= 1.f / (1.f + __expf(-a.w));
        *(float4*)(xc + (rbase + t) * DI + d4) = a;
        w0 = w1; w1 = w2; w2 = cur;
    }
}

// ---------------- x_proj: [4096,1024] x [64,1024]^T, 16 rows/CTA --------------
__global__ __launch_bounds__(256)
void xproj_kernel(const float* __restrict__ A, const float* __restrict__ B,
                  float* __restrict__ C) {
    __shared__ float As[16][68];
    __shared__ float Bs[64][68];
    int tid = threadIdx.x;
    int r0 = blockIdx.x * 16;
    int rr = tid >> 4;
    int ccq = tid & 15;
    float acc[4] = {0.f, 0.f, 0.f, 0.f};

    for (int k0 = 0; k0 < 1024; k0 += 64) {
        {
            int row = tid >> 4, seg = tid & 15;
            *(float4*)&As[row][seg * 4] =
                *(const float4*)(A + (size_t)(r0 + row) * 1024 + k0 + seg * 4);
        }
        #pragma unroll
        for (int i = 0; i < 4; i++) {
            int idx = tid + i * 256;
            int row = idx >> 4, seg = idx & 15;
            *(float4*)&Bs[row][seg * 4] =
                *(const float4*)(B + (size_t)row * 1024 + k0 + seg * 4);
        }
        __syncthreads();
        #pragma unroll 4
        for (int kk = 0; kk < 64; kk += 4) {
            float4 a = *(float4*)&As[rr][kk];
            #pragma unroll
            for (int j = 0; j < 4; j++) {
                float4 b = *(float4*)&Bs[ccq + 16 * j][kk];
                acc[j] = fmaf(a.x, b.x, acc[j]);
                acc[j] = fmaf(a.y, b.y, acc[j]);
                acc[j] = fmaf(a.z, b.z, acc[j]);
                acc[j] = fmaf(a.w, b.w, acc[j]);
            }
        }
        __syncthreads();
    }
    #pragma unroll
    for (int j = 0; j < 4; j++)
        C[(size_t)(r0 + rr) * 64 + ccq + 16 * j] = acc[j];
}

// ---------------- single-pass chained scan ------------------------------------
#define S2_XV   0
#define S2_DBC  (TC*16)
#define S2_DL   (S2_DBC + TC*64)
#define S2_DTW  (S2_DL + TC*16)
#define S2_DTB  (S2_DTW + 32*16)
#define S2_END  (S2_DTB + 16)
#define S2_Y    S2_END
#define SCAN_SMEM ((S2_END + TC*16) * 4)     // 59456 B

__global__ __launch_bounds__(256)
void scan_kernel(const float* __restrict__ xc,
                 const float* __restrict__ dbc,
                 const float* __restrict__ dt_w, const float* __restrict__ dt_b,
                 const float* __restrict__ xz,
                 const float* __restrict__ A_log,
                 const float* __restrict__ D_param,
                 float* __restrict__ Si, int* __restrict__ flags,
                 __half* __restrict__ yh) {
    extern __shared__ float sm[];
    int bx = blockIdx.x;
    int dt = bx & 63;
    int c  = (bx >> 6) & 15;
    int b  = bx >> 10;
    int tid = threadIdx.x;
    int n = tid & 15, dloc = tid >> 4;
    int d = dt * 16 + dloc;
    size_t row0 = (size_t)b * LQ + c * TC;

    #pragma unroll
    for (int i = 0; i < 2; i++) {
        int idx = tid + i * 256;
        int t = idx >> 2, q = idx & 3;
        *(float4*)&sm[S2_XV + t * 16 + q * 4] =
            *(const float4*)(xc + (row0 + t) * DI + dt * 16 + q * 4);
    }
    #pragma unroll
    for (int i = 0; i < 8; i++) {
        int idx = tid + i * 256;
        int t = idx >> 4, q = idx & 15;
        *(float4*)&sm[S2_DBC + t * 64 + q * 4] =
            *(const float4*)(dbc + (row0 + t) * 64 + q * 4);
    }
    #pragma unroll
    for (int i = 0; i < 2; i++) {
        int idx = tid + i * 256;
        int d2 = idx >> 5, r = idx & 31;
        sm[S2_DTW + r * 16 + d2] = dt_w[(dt * 16 + d2) * 32 + r];
    }
    if (tid < 16) sm[S2_DTB + tid] = dt_b[dt * 16 + tid];
    __syncthreads();

    float dl8[8];
    #pragma unroll
    for (int i = 0; i < 8; i++) {
        int idx = tid + i * 256;
        int t = idx >> 4, d2 = idx & 15;
        float a = sm[S2_DTB + d2];
        #pragma unroll
        for (int r = 0; r < 32; r++)
            a = fmaf(sm[S2_DBC + t * 64 + r], sm[S2_DTW + r * 16 + d2], a);
        dl8[i] = (a > 20.f) ? a : log1pf(__expf(a));
    }
    __syncthreads();
    #pragma unroll
    for (int i = 0; i < 8; i++) {
        int idx = tid + i * 256;
        int t = idx >> 4, d2 = idx & 15;
        sm[S2_DL + t * 16 + d2] = dl8[i];
    }
    __syncthreads();

    float An = -__expf(A_log[d * DSTATE + n]);
    float Dp = D_param[d];

    float h = 0.f, P = 1.f;
    #pragma unroll 4
    for (int t = 0; t < TC; t++) {
        float dl = sm[S2_DL + t * 16 + dloc];
        float dA = __expf(dl * An);
        h = fmaf(dA, h, dl * sm[S2_DBC + t * 64 + 32 + n] * sm[S2_XV + t * 16 + dloc]);
        P *= dA;
    }

    size_t lane_o = (((size_t)b * NCH + c) * DI + (size_t)dt * 16) * DSTATE + tid;
    float Hin = 0.f;
    if (c > 0) {
        int fi = b * NCH * 64 + (c - 1) * 64 + dt;
        int f;
        do {
            f = *(volatile int*)&flags[fi];
            if (!f) __nanosleep(64);
        } while (!f);
        __threadfence();
        size_t po = (((size_t)b * NCH + (c - 1)) * DI + (size_t)dt * 16) * DSTATE + tid;
        Hin = *(volatile float*)&Si[po];
    }
    Si[lane_o] = fmaf(P, Hin, h);
    __threadfence();
    __syncthreads();
    if (tid == 0) {
        __threadfence();
        *(volatile int*)&flags[b * NCH * 64 + c * 64 + dt] = 1;
    }

    h = Hin;
    #pragma unroll 4
    for (int t = 0; t < TC; t++) {
        float dl = sm[S2_DL + t * 16 + dloc];
        float xv = sm[S2_XV + t * 16 + dloc];
        float dA = __expf(dl * An);
        h = fmaf(dA, h, dl * sm[S2_DBC + t * 64 + 32 + n] * xv);
        float p = h * sm[S2_DBC + t * 64 + 48 + n];
        p += __shfl_xor_sync(0xffffffffu, p, 1);
        p += __shfl_xor_sync(0xffffffffu, p, 2);
        p += __shfl_xor_sync(0xffffffffu, p, 4);
        p += __shfl_xor_sync(0xffffffffu, p, 8);
        if (n == 0) sm[S2_Y + t * 16 + dloc] = p + Dp * xv;
    }
    __syncthreads();

    #pragma unroll
    for (int i = 0; i < 8; i++) {
        int idx = tid + i * 256;
        int t = idx >> 4, dl2 = idx & 15;
        size_t row = row0 + t;
        float zv = xz[row * 2048 + DI + dt * 16 + dl2];
        float sz = zv / (1.f + __expf(-zv));
        yh[row * DI + dt * 16 + dl2] = __float2half_rn(sm[S2_Y + t * 16 + dl2] * sz);
    }
}

// ---------------- host orchestration ------------------------------------------
extern "C" void kernel_launch(void* const* d_in, const int* in_sizes, int n_in,
                              void* d_out, int out_size) {
    const float* x      = (const float*)d_in[0];
    const float* n1_w   = (const float*)d_in[1];
    const float* n1_b   = (const float*)d_in[2];
    const float* mn_w   = (const float*)d_in[3];
    const float* mn_b   = (const float*)d_in[4];
    const float* in_w   = (const float*)d_in[5];
    const float* in_b   = (const float*)d_in[6];
    const float* conv_w = (const float*)d_in[7];
    const float* conv_b = (const float*)d_in[8];
    const float* xp_w   = (const float*)d_in[9];
    const float* dt_w   = (const float*)d_in[10];
    const float* dt_b   = (const float*)d_in[11];
    const float* A_log  = (const float*)d_in[12];
    const float* D_par  = (const float*)d_in[13];
    const float* out_w  = (const float*)d_in[14];
    const float* out_b  = (const float*)d_in[15];
    const float* n2_w   = (const float*)d_in[16];
    const float* n2_b   = (const float*)d_in[17];
    const float* kn_w   = (const float*)d_in[18];
    const float* kn_b   = (const float*)d_in[19];
    const float* grid   = (const float*)d_in[20];
    const float* spl_w  = (const float*)d_in[21];
    float* out = (float*)d_out;

    float *p_xz, *p_xc, *p_dbc, *p_x2, *p_Si;
    int *p_flag;
    __half *p_uh, *p_iwh, *p_yh, *p_owh, *p_bh, *p_swh;
    cudaGetSymbolAddress((void**)&p_xz,  g_xz);
    cudaGetSymbolAddress((void**)&p_xc,  g_xc);
    cudaGetSymbolAddress((void**)&p_dbc, g_dbc);
    cudaGetSymbolAddress((void**)&p_x2,  g_x2);
    cudaGetSymbolAddress((void**)&p_Si,  g_Si);
    cudaGetSymbolAddress((void**)&p_flag, g_flag);
    cudaGetSymbolAddress((void**)&p_uh,  g_uh);
    cudaGetSymbolAddress((void**)&p_iwh, g_iwh);
    cudaGetSymbolAddress((void**)&p_yh,  g_yh);
    cudaGetSymbolAddress((void**)&p_owh, g_owh);
    cudaGetSymbolAddress((void**)&p_bh,  g_bh);
    cudaGetSymbolAddress((void**)&p_swh, g_swh);

    cudaFuncSetAttribute(mgemm<EPI_BIAS>,
                         cudaFuncAttributeMaxDynamicSharedMemorySize, MG_SMEM);
    cudaFuncSetAttribute(mgemm<EPI_BIAS | EPI_RESID>,
                         cudaFuncAttributeMaxDynamicSharedMemorySize, MG_SMEM);
    cudaFuncSetAttribute(mgemm<EPI_RESID>,
                         cudaFuncAttributeMaxDynamicSharedMemorySize, MG_SMEM);
    cudaFuncSetAttribute(scan_kernel,
                         cudaFuncAttributeMaxDynamicSharedMemorySize, SCAN_SMEM);

    // 1. weights->fp16 + flag clear + u = LN(LN(x)) -> fp16   (merged launch)
    pre_kernel<<<WBLK + BL / 8, 256>>>(
        in_w, p_iwh, out_w, p_owh, spl_w, p_swh, p_flag,
        x, n1_w, n1_b, mn_w, mn_b, p_uh);

    // 2. xz = u @ in_w^T + in_b   [4096 x 2048, K=512]
    mgemm<EPI_BIAS><<<dim3(2048 / 128, BL / 128), 256, MG_SMEM>>>(
        p_uh, p_iwh, in_b, nullptr, p_xz, 2048, DQ);

    // 3. xc = silu(conv(xm))
    conv_silu_kernel<<<BQ * 256, 256>>>(p_xz, conv_w, conv_b, p_xc);

    // 4. dbc = xc @ xp_w^T  [4096 x 64, K=1024]
    xproj_kernel<<<BL / 16, 256>>>(p_xc, xp_w, p_dbc);

    // 5. single-pass chained scan (dt_proj fused) -> y fp16
    scan_kernel<<<BQ * NCH * 64, 256, SCAN_SMEM>>>(
        p_xc, p_dbc, dt_w, dt_b, p_xz, A_log, D_par, p_Si, p_flag, p_yh);

    // 6. x2 = x + y @ out_w^T + out_b  [4096 x 512, K=1024]
    mgemm<EPI_BIAS | EPI_RESID><<<dim3(DQ / 128, BL / 128), 256, MG_SMEM>>>(
        p_yh, p_owh, out_b, x, p_x2, DQ, DI);

    // 7. basis = sech2 of LN(LN(x2)) -> fp16 (LUT)
    ln2_basis_kernel<<<BL / 8, 256>>>(p_x2, n2_w, n2_b, kn_w, kn_b, grid, p_bh);

    // 8. out = x2 + basis @ spl_w^T  [4096 x 512, K=4096]
    mgemm<EPI_RESID><<<dim3(DQ / 128, BL / 128), 256, MG_SMEM>>>(
        p_bh, p_swh, nullptr, p_x2, out, DQ, 4096);

    (void)in_sizes; (void)n_in; (void)out_size;
}

// round 16
// speedup vs baseline: 1.0049x; 1.0049x over previous
#include <cuda_runtime.h>
#include <cuda_fp16.h>
#include <math.h>
#include <stdint.h>

// Problem constants
#define BQ 2
#define LQ 2048
#define DQ 512
#define DI 1024
#define BL (BQ*LQ)          // 4096 rows
#define DSTATE 16
#define NG 8
#define TC 128              // scan chunk length
#define NCH (LQ/TC)         // 16 chunks

// ---------------- device scratch ---------------------------------------------
__device__ float g_xz[(size_t)BL*2048];      // in_proj output (xm | z), fp32
__device__ float g_xc[(size_t)BL*DI];        // conv+silu
__device__ float g_dbc[BL*64];               // x_proj output
__device__ float g_x2[BL*DQ];                // x + mix

__device__ float g_Si[(size_t)BQ*NCH*DI*DSTATE]; // inclusive chunk states
__device__ int   g_flag[BQ*NCH*64];              // chunk-ready flags

__device__ __half g_uh[(size_t)BL*DQ];           // ln2(x) fp16
__device__ __half g_iwh[2048*DQ];                // in_w fp16
__device__ __half g_yh[(size_t)BL*DI];           // scan out fp16
__device__ __half g_owh[DQ*DI];                  // out_w fp16
__device__ __half g_bh[(size_t)BL*4096];         // KAN basis fp16
__device__ __half g_swh[DQ*4096];                // spl_w fp16

// ---------------- PTX helpers -------------------------------------------------
#define CP_ASYNC16(s, g) \
    asm volatile("cp.async.cg.shared.global [%0], [%1], 16;" :: "r"(s), "l"(g))
#define CP_COMMIT() asm volatile("cp.async.commit_group;" ::: "memory")
#define CP_WAIT(n)  asm volatile("cp.async.wait_group %0;" :: "n"(n) : "memory")

__device__ __forceinline__ void ldsm4(uint32_t* r, uint32_t addr) {
    asm volatile("ldmatrix.sync.aligned.m8n8.x4.shared.b16 {%0,%1,%2,%3}, [%4];"
                 : "=r"(r[0]), "=r"(r[1]), "=r"(r[2]), "=r"(r[3]) : "r"(addr));
}
__device__ __forceinline__ void mma_f16(float* c, const uint32_t* a, const uint32_t* b) {
    asm volatile("mma.sync.aligned.m16n8k16.row.col.f32.f16.f16.f32 "
                 "{%0,%1,%2,%3}, {%4,%5,%6,%7}, {%8,%9}, {%0,%1,%2,%3};"
                 : "+f"(c[0]), "+f"(c[1]), "+f"(c[2]), "+f"(c[3])
                 : "r"(a[0]), "r"(a[1]), "r"(a[2]), "r"(a[3]),
                   "r"(b[0]), "r"(b[1]));
}

// ---------------- epilogue flags ---------------------------------------------
#define EPI_BIAS 1
#define EPI_RESID 2

// ---------------- fp16 NT GEMM via mma.sync, 3-stage pipeline -----------------
#define MG_STRIDE 80
#define MG_A 10240
#define MG_STAGE (2 * MG_A)
#define MG_SMEM (3 * MG_STAGE)     // 61440

template<int EPI>
__global__ __launch_bounds__(256, 2)
void mgemm(const __half* __restrict__ Ah, const __half* __restrict__ Bh,
           const float* __restrict__ bias, const float* __restrict__ resid,
           float* __restrict__ C, int N, int K) {
    extern __shared__ __align__(128) char smem[];
    uint32_t sb = (uint32_t)__cvta_generic_to_shared(smem);
    int tid = threadIdx.x;
    int lane = tid & 31, warp = tid >> 5;
    int bm = blockIdx.y * 128, bn = blockIdx.x * 128;
    int wm = (warp >> 2) * 64;
    int wn = (warp & 3) * 32;

    int nc = K / 32;

    auto issue = [&](int c) {
        int k0 = c * 32;
        uint32_t bufb = sb + (uint32_t)(c % 3) * MG_STAGE;
        #pragma unroll
        for (int i = 0; i < 2; i++) {
            int idx = tid + i * 256;
            int row = idx >> 2, seg = idx & 3;
            CP_ASYNC16(bufb + row * MG_STRIDE + seg * 16,
                       Ah + (size_t)(bm + row) * K + k0 + seg * 8);
        }
        #pragma unroll
        for (int i = 0; i < 2; i++) {
            int idx = tid + i * 256;
            int row = idx >> 2, seg = idx & 3;
            CP_ASYNC16(bufb + MG_A + row * MG_STRIDE + seg * 16,
                       Bh + (size_t)(bn + row) * K + k0 + seg * 8);
        }
        CP_COMMIT();
    };

    float acc[4][4][4];
    #pragma unroll
    for (int mt = 0; mt < 4; mt++)
        #pragma unroll
        for (int nt = 0; nt < 4; nt++)
            #pragma unroll
            for (int q = 0; q < 4; q++) acc[mt][nt][q] = 0.f;

    issue(0); issue(1); issue(2);

    for (int c = 0; c < nc; c++) {
        int left = nc - 1 - c;
        if (left >= 2)      { CP_WAIT(2); }
        else if (left == 1) { CP_WAIT(1); }
        else                { CP_WAIT(0); }
        __syncthreads();
        uint32_t base = sb + (uint32_t)(c % 3) * MG_STAGE;
        uint32_t rsel = (lane & 15) * MG_STRIDE;
        #pragma unroll
        for (int kst = 0; kst < 2; kst++) {
            uint32_t kb = kst * 32 + (lane >> 4) * 16;
            uint32_t bf[4][2], af[4][4];
            #pragma unroll
            for (int p = 0; p < 2; p++) {
                uint32_t r[4];
                ldsm4(r, base + MG_A + (wn + p * 16) * MG_STRIDE + rsel + kb);
                bf[p*2][0] = r[0]; bf[p*2][1] = r[2];
                bf[p*2+1][0] = r[1]; bf[p*2+1][1] = r[3];
            }
            #pragma unroll
            for (int mt = 0; mt < 4; mt++)
                ldsm4(af[mt], base + (wm + mt * 16) * MG_STRIDE + rsel + kb);
            #pragma unroll
            for (int mt = 0; mt < 4; mt++)
                #pragma unroll
                for (int nt = 0; nt < 4; nt++)
                    mma_f16(acc[mt][nt], af[mt], bf[nt]);
        }
        __syncthreads();
        if (c + 3 < nc) issue(c + 3);
    }

    int g = lane >> 2, tig = lane & 3;
    #pragma unroll
    for (int mt = 0; mt < 4; mt++) {
        size_t r0 = (size_t)bm + wm + mt * 16 + g;
        size_t r1 = r0 + 8;
        #pragma unroll
        for (int nt = 0; nt < 4; nt++) {
            int col = bn + wn + nt * 8 + tig * 2;
            float2 v0 = make_float2(acc[mt][nt][0], acc[mt][nt][1]);
            float2 v1 = make_float2(acc[mt][nt][2], acc[mt][nt][3]);
            if (EPI & EPI_BIAS) {
                float b0 = bias[col], b1 = bias[col + 1];
                v0.x += b0; v0.y += b1; v1.x += b0; v1.y += b1;
            }
            if (EPI & EPI_RESID) {
                const float* rp0 = resid + r0 * N + col;
                const float* rp1 = resid + r1 * N + col;
                v0.x += rp0[0]; v0.y += rp0[1];
                v1.x += rp1[0]; v1.y += rp1[1];
            }
            *(float2*)(C + r0 * N + col) = v0;
            *(float2*)(C + r1 * N + col) = v1;
        }
    }
}

// ---------------- double-LN core ----------------------------------------------
__device__ __forceinline__ void ln2_core(float4 v[4], int lane,
                                         const float* __restrict__ w1,
                                         const float* __restrict__ b1,
                                         const float* __restrict__ w2,
                                         const float* __restrict__ b2) {
    #pragma unroll
    for (int pass = 0; pass < 2; pass++) {
        const float* wz = pass ? w2 : w1;
        const float* bz = pass ? b2 : b1;
        float s = 0.f;
        #pragma unroll
        for (int i = 0; i < 4; i++) s += v[i].x + v[i].y + v[i].z + v[i].w;
        #pragma unroll
        for (int o = 16; o > 0; o >>= 1) s += __shfl_xor_sync(0xffffffffu, s, o);
        float mu = s * (1.f / DQ);
        float q = 0.f;
        #pragma unroll
        for (int i = 0; i < 4; i++) {
            float a = v[i].x - mu, b = v[i].y - mu, c = v[i].z - mu, d = v[i].w - mu;
            q += a * a + b * b + c * c + d * d;
        }
        #pragma unroll
        for (int o = 16; o > 0; o >>= 1) q += __shfl_xor_sync(0xffffffffu, q, o);
        float rs = rsqrtf(q * (1.f / DQ) + 1e-5f);
        #pragma unroll
        for (int i = 0; i < 4; i++) {
            float4 w = ((const float4*)wz)[lane + i * 32];
            float4 b = ((const float4*)bz)[lane + i * 32];
            v[i].x = (v[i].x - mu) * rs * w.x + b.x;
            v[i].y = (v[i].y - mu) * rs * w.y + b.y;
            v[i].z = (v[i].z - mu) * rs * w.z + b.z;
            v[i].w = (v[i].w - mu) * rs * w.w + b.w;
        }
    }
}

// ---------------- merged: weight convert + flag clear + ln2(x) -> fp16 --------
#define W1N (2048*DQ/4)
#define W2N (DQ*DI/4)
#define W3N (DQ*4096/4)
#define WTOT (W1N + W2N + W3N)              // 917504
#define WBLK ((WTOT + 255) / 256)           // 3584
__global__ __launch_bounds__(256)
void pre_kernel(const float* __restrict__ s1, __half* __restrict__ h1,
                const float* __restrict__ s2, __half* __restrict__ h2,
                const float* __restrict__ s3, __half* __restrict__ h3,
                int* __restrict__ flags,
                const float* __restrict__ x,
                const float* __restrict__ w1, const float* __restrict__ b1,
                const float* __restrict__ w2, const float* __restrict__ b2,
                __half* __restrict__ oh) {
    if (blockIdx.x < WBLK) {
        int i = blockIdx.x * 256 + threadIdx.x;
        if (i < BQ * NCH * 64) flags[i] = 0;
        const float* s; __half* h; int j;
        if (i < W1N)            { s = s1; h = h1; j = i; }
        else if (i < W1N + W2N) { s = s2; h = h2; j = i - W1N; }
        else if (i < WTOT)      { s = s3; h = h3; j = i - W1N - W2N; }
        else return;
        float4 v = ((const float4*)s)[j];
        __half2* hp = (__half2*)h;
        hp[2 * j + 0] = __halves2half2(__float2half_rn(v.x), __float2half_rn(v.y));
        hp[2 * j + 1] = __halves2half2(__float2half_rn(v.z), __float2half_rn(v.w));
        return;
    }
    int lane = threadIdx.x & 31;
    int row = (blockIdx.x - WBLK) * 8 + (threadIdx.x >> 5);
    const float4* xr = (const float4*)(x + (size_t)row * DQ);
    float4 v[4];
    #pragma unroll
    for (int i = 0; i < 4; i++) v[i] = xr[lane + i * 32];
    ln2_core(v, lane, w1, b1, w2, b2);
    __half2* hp = (__half2*)(oh + (size_t)row * DQ);
    #pragma unroll
    for (int i = 0; i < 4; i++) {
        int j = (lane + i * 32) * 2;
        hp[j + 0] = __halves2half2(__float2half_rn(v[i].x), __float2half_rn(v[i].y));
        hp[j + 1] = __halves2half2(__float2half_rn(v[i].z), __float2half_rn(v[i].w));
    }
}

// ---------------- fused ln2 + KAN basis (exp identity) -> fp16 ----------------
__global__ __launch_bounds__(256)
void ln2_basis_kernel(const float* __restrict__ x,
                      const float* __restrict__ w1, const float* __restrict__ b1,
                      const float* __restrict__ w2, const float* __restrict__ b2,
                      const float* __restrict__ grid,
                      __half* __restrict__ bh) {
    const float INV = 1.0f / 0.33f;
    int lane = threadIdx.x & 31;
    int row = blockIdx.x * 8 + (threadIdx.x >> 5);
    const float4* xr = (const float4*)(x + (size_t)row * DQ);
    float4 v[4];
    #pragma unroll
    for (int i = 0; i < 4; i++) v[i] = xr[lane + i * 32];
    ln2_core(v, lane, w1, b1, w2, b2);

    float cg[8];
    #pragma unroll
    for (int g = 0; g < 8; g++) cg[g] = __expf(2.f * __ldg(grid + g) * INV);

    __half* brow = bh + (size_t)row * 4096;
    #pragma unroll
    for (int i = 0; i < 4; i++) {
        float kv4[4] = {v[i].x, v[i].y, v[i].z, v[i].w};
        #pragma unroll
        for (int c = 0; c < 4; c++) {
            float kv = fminf(fmaxf(kv4[c], -14.f), 14.f);
            float E = __expf(-2.f * kv * INV);
            int d = (lane + i * 32) * 4 + c;
            __half hs[8];
            #pragma unroll
            for (int g = 0; g < 8; g++) {
                float e = E * cg[g];
                float op = 1.f + e;
                float val = (e > 1e30f) ? 0.f : __fdividef(4.f * e, op * op);
                hs[g] = __float2half_rn(val);
            }
            *(uint4*)(brow + d * 8) = *(uint4*)hs;
        }
    }
}

// ---------------- causal conv+silu, sliding-window, seg=8 ---------------------
__global__ __launch_bounds__(256)
void conv_silu_kernel(const float* __restrict__ xz,
                      const float* __restrict__ cw,
                      const float* __restrict__ cb,
                      float* __restrict__ xc) {
    int b = blockIdx.x >> 8;
    int seg = blockIdx.x & 255;
    int d4 = threadIdx.x * 4;
    int t0 = seg * 8;
    size_t rbase = (size_t)b * LQ;

    float4 cw0 = *(const float4*)(cw + (d4 + 0) * 4);
    float4 cw1 = *(const float4*)(cw + (d4 + 1) * 4);
    float4 cw2 = *(const float4*)(cw + (d4 + 2) * 4);
    float4 cw3 = *(const float4*)(cw + (d4 + 3) * 4);
    float4 bias = *(const float4*)(cb + d4);

    float4 w0, w1, w2;
    {
        int t = t0 - 3;
        w0 = (t >= 0) ? *(const float4*)(xz + (rbase + t) * 2048 + d4)
                      : make_float4(0.f, 0.f, 0.f, 0.f);
        t = t0 - 2;
        w1 = (t >= 0) ? *(const float4*)(xz + (rbase + t) * 2048 + d4)
                      : make_float4(0.f, 0.f, 0.f, 0.f);
        t = t0 - 1;
        w2 = (t >= 0) ? *(const float4*)(xz + (rbase + t) * 2048 + d4)
                      : make_float4(0.f, 0.f, 0.f, 0.f);
    }
    #pragma unroll
    for (int tt = 0; tt < 8; tt++) {
        int t = t0 + tt;
        float4 cur = *(const float4*)(xz + (rbase + t) * 2048 + d4);
        float4 a = bias;
        a.x = fmaf(w0.x, cw0.x, fmaf(w1.x, cw0.y, fmaf(w2.x, cw0.z, fmaf(cur.x, cw0.w, a.x))));
        a.y = fmaf(w0.y, cw1.x, fmaf(w1.y, cw1.y, fmaf(w2.y, cw1.z, fmaf(cur.y, cw1.w, a.y))));
        a.z = fmaf(w0.z, cw2.x, fmaf(w1.z, cw2.y, fmaf(w2.z, cw2.z, fmaf(cur.z, cw2.w, a.z))));
        a.w = fmaf(w0.w, cw3.x, fmaf(w1.w, cw3.y, fmaf(w2.w, cw3.z, fmaf(cur.w, cw3.w, a.w))));
        a.x *= 1.f / (1.f + __expf(-a.x));
        a.y *= 1.f / (1.f + __expf(-a.y));
        a.z *= 1.f / (1.f + __expf(-a.z));
        a.w *= 1.f / (1.f + __expf(-a.w));
        *(float4*)(xc + (rbase + t) * DI + d4) = a;
        w0 = w1; w1 = w2; w2 = cur;
    }
}

// ---------------- x_proj: 64x64 tile, 4x4 per thread, aligned layout ----------
// dbc[4096 x 64] = xc @ xp_w^T, K=1024. grid 64 CTAs, block 256.
// stride 36 floats (144 B = 9x16B): float4 reads aligned.
// thread rows {tr+16i} (tr=tid>>4: broadcast), cols {tc+16j} (tc=tid&15:
// adjacent threads 36 floats apart = 4 banks -> conflict-free LDS.128 phases).
#define XP_STR 36
__global__ __launch_bounds__(256)
void xproj_kernel(const float* __restrict__ A, const float* __restrict__ B,
                  float* __restrict__ C) {
    __shared__ __align__(16) float As[64][XP_STR];
    __shared__ __align__(16) float Bs[64][XP_STR];
    int tid = threadIdx.x;
    int r0 = blockIdx.x * 64;
    int tr = tid >> 4;            // 0..15
    int tc = tid & 15;            // 0..15

    float acc[4][4];
    #pragma unroll
    for (int i = 0; i < 4; i++)
        #pragma unroll
        for (int j = 0; j < 4; j++) acc[i][j] = 0.f;

    for (int k0 = 0; k0 < 1024; k0 += 32) {
        #pragma unroll
        for (int i = 0; i < 2; i++) {
            int idx = tid + i * 256;
            int row = idx >> 3, seg = idx & 7;
            *(float4*)&As[row][seg * 4] =
                *(const float4*)(A + (size_t)(r0 + row) * 1024 + k0 + seg * 4);
            *(float4*)&Bs[row][seg * 4] =
                *(const float4*)(B + (size_t)row * 1024 + k0 + seg * 4);
        }
        __syncthreads();
        #pragma unroll
        for (int kk = 0; kk < 32; kk += 4) {
            float4 av[4], bv[4];
            #pragma unroll
            for (int i = 0; i < 4; i++) av[i] = *(float4*)&As[tr + 16 * i][kk];
            #pragma unroll
            for (int j = 0; j < 4; j++) bv[j] = *(float4*)&Bs[tc + 16 * j][kk];
            #pragma unroll
            for (int i = 0; i < 4; i++)
                #pragma unroll
                for (int j = 0; j < 4; j++) {
                    acc[i][j] = fmaf(av[i].x, bv[j].x, acc[i][j]);
                    acc[i][j] = fmaf(av[i].y, bv[j].y, acc[i][j]);
                    acc[i][j] = fmaf(av[i].z, bv[j].z, acc[i][j]);
                    acc[i][j] = fmaf(av[i].w, bv[j].w, acc[i][j]);
                }
        }
        __syncthreads();
    }
    #pragma unroll
    for (int i = 0; i < 4; i++)
        #pragma unroll
        for (int j = 0; j < 4; j++)
            C[(size_t)(r0 + tr + 16 * i) * 64 + tc + 16 * j] = acc[i][j];
}

// ---------------- single-pass chained scan ------------------------------------
#define S2_XV   0
#define S2_DBC  (TC*16)
#define S2_DL   (S2_DBC + TC*64)
#define S2_DTW  (S2_DL + TC*16)
#define S2_DTB  (S2_DTW + 32*16)
#define S2_END  (S2_DTB + 16)
#define S2_Y    S2_END
#define SCAN_SMEM ((S2_END + TC*16) * 4)     // 59456 B

__global__ __launch_bounds__(256)
void scan_kernel(const float* __restrict__ xc,
                 const float* __restrict__ dbc,
                 const float* __restrict__ dt_w, const float* __restrict__ dt_b,
                 const float* __restrict__ xz,
                 const float* __restrict__ A_log,
                 const float* __restrict__ D_param,
                 float* __restrict__ Si, int* __restrict__ flags,
                 __half* __restrict__ yh) {
    extern __shared__ float sm[];
    int bx = blockIdx.x;
    int dt = bx & 63;
    int c  = (bx >> 6) & 15;
    int b  = bx >> 10;
    int tid = threadIdx.x;
    int n = tid & 15, dloc = tid >> 4;
    int d = dt * 16 + dloc;
    size_t row0 = (size_t)b * LQ + c * TC;

    #pragma unroll
    for (int i = 0; i < 2; i++) {
        int idx = tid + i * 256;
        int t = idx >> 2, q = idx & 3;
        *(float4*)&sm[S2_XV + t * 16 + q * 4] =
            *(const float4*)(xc + (row0 + t) * DI + dt * 16 + q * 4);
    }
    #pragma unroll
    for (int i = 0; i < 8; i++) {
        int idx = tid + i * 256;
        int t = idx >> 4, q = idx & 15;
        *(float4*)&sm[S2_DBC + t * 64 + q * 4] =
            *(const float4*)(dbc + (row0 + t) * 64 + q * 4);
    }
    #pragma unroll
    for (int i = 0; i < 2; i++) {
        int idx = tid + i * 256;
        int d2 = idx >> 5, r = idx & 31;
        sm[S2_DTW + r * 16 + d2] = dt_w[(dt * 16 + d2) * 32 + r];
    }
    if (tid < 16) sm[S2_DTB + tid] = dt_b[dt * 16 + tid];
    __syncthreads();

    float dl8[8];
    #pragma unroll
    for (int i = 0; i < 8; i++) {
        int idx = tid + i * 256;
        int t = idx >> 4, d2 = idx & 15;
        float a = sm[S2_DTB + d2];
        #pragma unroll
        for (int r = 0; r < 32; r++)
            a = fmaf(sm[S2_DBC + t * 64 + r], sm[S2_DTW + r * 16 + d2], a);
        dl8[i] = (a > 20.f) ? a : log1pf(__expf(a));
    }
    __syncthreads();
    #pragma unroll
    for (int i = 0; i < 8; i++) {
        int idx = tid + i * 256;
        int t = idx >> 4, d2 = idx & 15;
        sm[S2_DL + t * 16 + d2] = dl8[i];
    }
    __syncthreads();

    float An = -__expf(A_log[d * DSTATE + n]);
    float Dp = D_param[d];

    float h = 0.f, P = 1.f;
    #pragma unroll 4
    for (int t = 0; t < TC; t++) {
        float dl = sm[S2_DL + t * 16 + dloc];
        float dA = __expf(dl * An);
        h = fmaf(dA, h, dl * sm[S2_DBC + t * 64 + 32 + n] * sm[S2_XV + t * 16 + dloc]);
        P *= dA;
    }

    size_t lane_o = (((size_t)b * NCH + c) * DI + (size_t)dt * 16) * DSTATE + tid;
    float Hin = 0.f;
    if (c > 0) {
        int fi = b * NCH * 64 + (c - 1) * 64 + dt;
        int f;
        do {
            f = *(volatile int*)&flags[fi];
            if (!f) __nanosleep(64);
        } while (!f);
        __threadfence();
        size_t po = (((size_t)b * NCH + (c - 1)) * DI + (size_t)dt * 16) * DSTATE + tid;
        Hin = *(volatile float*)&Si[po];
    }
    Si[lane_o] = fmaf(P, Hin, h);
    __threadfence();
    __syncthreads();
    if (tid == 0) {
        __threadfence();
        *(volatile int*)&flags[b * NCH * 64 + c * 64 + dt] = 1;
    }

    h = Hin;
    #pragma unroll 4
    for (int t = 0; t < TC; t++) {
        float dl = sm[S2_DL + t * 16 + dloc];
        float xv = sm[S2_XV + t * 16 + dloc];
        float dA = __expf(dl * An);
        h = fmaf(dA, h, dl * sm[S2_DBC + t * 64 + 32 + n] * xv);
        float p = h * sm[S2_DBC + t * 64 + 48 + n];
        p += __shfl_xor_sync(0xffffffffu, p, 1);
        p += __shfl_xor_sync(0xffffffffu, p, 2);
        p += __shfl_xor_sync(0xffffffffu, p, 4);
        p += __shfl_xor_sync(0xffffffffu, p, 8);
        if (n == 0) sm[S2_Y + t * 16 + dloc] = p + Dp * xv;
    }
    __syncthreads();

    #pragma unroll
    for (int i = 0; i < 8; i++) {
        int idx = tid + i * 256;
        int t = idx >> 4, dl2 = idx & 15;
        size_t row = row0 + t;
        float zv = xz[row * 2048 + DI + dt * 16 + dl2];
        float sz = zv / (1.f + __expf(-zv));
        yh[row * DI + dt * 16 + dl2] = __float2half_rn(sm[S2_Y + t * 16 + dl2] * sz);
    }
}

// ---------------- host orchestration ------------------------------------------
extern "C" void kernel_launch(void* const* d_in, const int* in_sizes, int n_in,
                              void* d_out, int out_size) {
    const float* x      = (const float*)d_in[0];
    const float* n1_w   = (const float*)d_in[1];
    const float* n1_b   = (const float*)d_in[2];
    const float* mn_w   = (const float*)d_in[3];
    const float* mn_b   = (const float*)d_in[4];
    const float* in_w   = (const float*)d_in[5];
    const float* in_b   = (const float*)d_in[6];
    const float* conv_w = (const float*)d_in[7];
    const float* conv_b = (const float*)d_in[8];
    const float* xp_w   = (const float*)d_in[9];
    const float* dt_w   = (const float*)d_in[10];
    const float* dt_b   = (const float*)d_in[11];
    const float* A_log  = (const float*)d_in[12];
    const float* D_par  = (const float*)d_in[13];
    const float* out_w  = (const float*)d_in[14];
    const float* out_b  = (const float*)d_in[15];
    const float* n2_w   = (const float*)d_in[16];
    const float* n2_b   = (const float*)d_in[17];
    const float* kn_w   = (const float*)d_in[18];
    const float* kn_b   = (const float*)d_in[19];
    const float* grid   = (const float*)d_in[20];
    const float* spl_w  = (const float*)d_in[21];
    float* out = (float*)d_out;

    float *p_xz, *p_xc, *p_dbc, *p_x2, *p_Si;
    int *p_flag;
    __half *p_uh, *p_iwh, *p_yh, *p_owh, *p_bh, *p_swh;
    cudaGetSymbolAddress((void**)&p_xz,  g_xz);
    cudaGetSymbolAddress((void**)&p_xc,  g_xc);
    cudaGetSymbolAddress((void**)&p_dbc, g_dbc);
    cudaGetSymbolAddress((void**)&p_x2,  g_x2);
    cudaGetSymbolAddress((void**)&p_Si,  g_Si);
    cudaGetSymbolAddress((void**)&p_flag, g_flag);
    cudaGetSymbolAddress((void**)&p_uh,  g_uh);
    cudaGetSymbolAddress((void**)&p_iwh, g_iwh);
    cudaGetSymbolAddress((void**)&p_yh,  g_yh);
    cudaGetSymbolAddress((void**)&p_owh, g_owh);
    cudaGetSymbolAddress((void**)&p_bh,  g_bh);
    cudaGetSymbolAddress((void**)&p_swh, g_swh);

    cudaFuncSetAttribute(mgemm<EPI_BIAS>,
                         cudaFuncAttributeMaxDynamicSharedMemorySize, MG_SMEM);
    cudaFuncSetAttribute(mgemm<EPI_BIAS | EPI_RESID>,
                         cudaFuncAttributeMaxDynamicSharedMemorySize, MG_SMEM);
    cudaFuncSetAttribute(mgemm<EPI_RESID>,
                         cudaFuncAttributeMaxDynamicSharedMemorySize, MG_SMEM);
    cudaFuncSetAttribute(scan_kernel,
                         cudaFuncAttributeMaxDynamicSharedMemorySize, SCAN_SMEM);

    // 1. weights->fp16 + flag clear + u = LN(LN(x)) -> fp16   (merged launch)
    pre_kernel<<<WBLK + BL / 8, 256>>>(
        in_w, p_iwh, out_w, p_owh, spl_w, p_swh, p_flag,
        x, n1_w, n1_b, mn_w, mn_b, p_uh);

    // 2. xz = u @ in_w^T + in_b   [4096 x 2048, K=512]
    mgemm<EPI_BIAS><<<dim3(2048 / 128, BL / 128), 256, MG_SMEM>>>(
        p_uh, p_iwh, in_b, nullptr, p_xz, 2048, DQ);

    // 3. xc = silu(conv(xm))
    conv_silu_kernel<<<BQ * 256, 256>>>(p_xz, conv_w, conv_b, p_xc);

    // 4. dbc = xc @ xp_w^T  [4096 x 64, K=1024]  (64x64 register-tiled)
    xproj_kernel<<<BL / 64, 256>>>(p_xc, xp_w, p_dbc);

    // 5. single-pass chained scan (dt_proj fused) -> y fp16
    scan_kernel<<<BQ * NCH * 64, 256, SCAN_SMEM>>>(
        p_xc, p_dbc, dt_w, dt_b, p_xz, A_log, D_par, p_Si, p_flag, p_yh);

    // 6. x2 = x + y @ out_w^T + out_b  [4096 x 512, K=1024]
    mgemm<EPI_BIAS | EPI_RESID><<<dim3(DQ / 128, BL / 128), 256, MG_SMEM>>>(
        p_yh, p_owh, out_b, x, p_x2, DQ, DI);

    // 7. basis = sech2 of LN(LN(x2)) -> fp16 (exp identity)
    ln2_basis_kernel<<<BL / 8, 256>>>(p_x2, n2_w, n2_b, kn_w, kn_b, grid, p_bh);

    // 8. out = x2 + basis @ spl_w^T  [4096 x 512, K=4096]
    mgemm<EPI_RESID><<<dim3(DQ / 128, BL / 128), 256, MG_SMEM>>>(
        p_bh, p_swh, nullptr, p_x2, out, DQ, 4096);

    (void)in_sizes; (void)n_in; (void)out_size;
}

// round 17
// speedup vs baseline: 1.0790x; 1.0738x over previous
#include <cuda_runtime.h>
#include <cuda_fp16.h>
#include <math.h>
#include <stdint.h>

// Problem constants
#define BQ 2
#define LQ 2048
#define DQ 512
#define DI 1024
#define BL (BQ*LQ)          // 4096 rows
#define DSTATE 16
#define NG 8
#define TC 128              // scan chunk length
#define NCH (LQ/TC)         // 16 chunks

// ---------------- device scratch ---------------------------------------------
__device__ float g_xz[(size_t)BL*2048];      // in_proj output (xm | z), fp32
__device__ float g_xc[(size_t)BL*DI];        // conv+silu fp32
__device__ float g_dbc[(size_t)BL*128];      // x_proj output (padded N=128)
__device__ float g_x2[BL*DQ];                // x + mix

__device__ float g_Si[(size_t)BQ*NCH*DI*DSTATE]; // inclusive chunk states
__device__ int   g_flag[BQ*NCH*64];              // chunk-ready flags

__device__ __half g_uh[(size_t)BL*DQ];           // ln2(x) fp16
__device__ __half g_iwh[2048*DQ];                // in_w fp16
__device__ __half g_xch[(size_t)BL*DI];          // xc fp16 shadow
__device__ __half g_xpwh[128*DI];                // xp_w fp16, zero-padded to 128 rows
__device__ __half g_yh[(size_t)BL*DI];           // scan out fp16
__device__ __half g_owh[DQ*DI];                  // out_w fp16
__device__ __half g_bh[(size_t)BL*4096];         // KAN basis fp16
__device__ __half g_swh[DQ*4096];                // spl_w fp16

// ---------------- PTX helpers -------------------------------------------------
#define CP_ASYNC16(s, g) \
    asm volatile("cp.async.cg.shared.global [%0], [%1], 16;" :: "r"(s), "l"(g))
#define CP_COMMIT() asm volatile("cp.async.commit_group;" ::: "memory")
#define CP_WAIT(n)  asm volatile("cp.async.wait_group %0;" :: "n"(n) : "memory")

__device__ __forceinline__ void ldsm4(uint32_t* r, uint32_t addr) {
    asm volatile("ldmatrix.sync.aligned.m8n8.x4.shared.b16 {%0,%1,%2,%3}, [%4];"
                 : "=r"(r[0]), "=r"(r[1]), "=r"(r[2]), "=r"(r[3]) : "r"(addr));
}
__device__ __forceinline__ void mma_f16(float* c, const uint32_t* a, const uint32_t* b) {
    asm volatile("mma.sync.aligned.m16n8k16.row.col.f32.f16.f16.f32 "
                 "{%0,%1,%2,%3}, {%4,%5,%6,%7}, {%8,%9}, {%0,%1,%2,%3};"
                 : "+f"(c[0]), "+f"(c[1]), "+f"(c[2]), "+f"(c[3])
                 : "r"(a[0]), "r"(a[1]), "r"(a[2]), "r"(a[3]),
                   "r"(b[0]), "r"(b[1]));
}

// ---------------- epilogue flags ---------------------------------------------
#define EPI_BIAS 1
#define EPI_RESID 2

// ---------------- fp16 NT GEMM via mma.sync, 3-stage pipeline -----------------
#define MG_STRIDE 80
#define MG_A 10240
#define MG_STAGE (2 * MG_A)
#define MG_SMEM (3 * MG_STAGE)     // 61440

template<int EPI>
__global__ __launch_bounds__(256, 2)
void mgemm(const __half* __restrict__ Ah, const __half* __restrict__ Bh,
           const float* __restrict__ bias, const float* __restrict__ resid,
           float* __restrict__ C, int N, int K) {
    extern __shared__ __align__(128) char smem[];
    uint32_t sb = (uint32_t)__cvta_generic_to_shared(smem);
    int tid = threadIdx.x;
    int lane = tid & 31, warp = tid >> 5;
    int bm = blockIdx.y * 128, bn = blockIdx.x * 128;
    int wm = (warp >> 2) * 64;
    int wn = (warp & 3) * 32;

    int nc = K / 32;

    auto issue = [&](int c) {
        int k0 = c * 32;
        uint32_t bufb = sb + (uint32_t)(c % 3) * MG_STAGE;
        #pragma unroll
        for (int i = 0; i < 2; i++) {
            int idx = tid + i * 256;
            int row = idx >> 2, seg = idx & 3;
            CP_ASYNC16(bufb + row * MG_STRIDE + seg * 16,
                       Ah + (size_t)(bm + row) * K + k0 + seg * 8);
        }
        #pragma unroll
        for (int i = 0; i < 2; i++) {
            int idx = tid + i * 256;
            int row = idx >> 2, seg = idx & 3;
            CP_ASYNC16(bufb + MG_A + row * MG_STRIDE + seg * 16,
                       Bh + (size_t)(bn + row) * K + k0 + seg * 8);
        }
        CP_COMMIT();
    };

    float acc[4][4][4];
    #pragma unroll
    for (int mt = 0; mt < 4; mt++)
        #pragma unroll
        for (int nt = 0; nt < 4; nt++)
            #pragma unroll
            for (int q = 0; q < 4; q++) acc[mt][nt][q] = 0.f;

    issue(0); issue(1); issue(2);

    for (int c = 0; c < nc; c++) {
        int left = nc - 1 - c;
        if (left >= 2)      { CP_WAIT(2); }
        else if (left == 1) { CP_WAIT(1); }
        else                { CP_WAIT(0); }
        __syncthreads();
        uint32_t base = sb + (uint32_t)(c % 3) * MG_STAGE;
        uint32_t rsel = (lane & 15) * MG_STRIDE;
        #pragma unroll
        for (int kst = 0; kst < 2; kst++) {
            uint32_t kb = kst * 32 + (lane >> 4) * 16;
            uint32_t bf[4][2], af[4][4];
            #pragma unroll
            for (int p = 0; p < 2; p++) {
                uint32_t r[4];
                ldsm4(r, base + MG_A + (wn + p * 16) * MG_STRIDE + rsel + kb);
                bf[p*2][0] = r[0]; bf[p*2][1] = r[2];
                bf[p*2+1][0] = r[1]; bf[p*2+1][1] = r[3];
            }
            #pragma unroll
            for (int mt = 0; mt < 4; mt++)
                ldsm4(af[mt], base + (wm + mt * 16) * MG_STRIDE + rsel + kb);
            #pragma unroll
            for (int mt = 0; mt < 4; mt++)
                #pragma unroll
                for (int nt = 0; nt < 4; nt++)
                    mma_f16(acc[mt][nt], af[mt], bf[nt]);
        }
        __syncthreads();
        if (c + 3 < nc) issue(c + 3);
    }

    int g = lane >> 2, tig = lane & 3;
    #pragma unroll
    for (int mt = 0; mt < 4; mt++) {
        size_t r0 = (size_t)bm + wm + mt * 16 + g;
        size_t r1 = r0 + 8;
        #pragma unroll
        for (int nt = 0; nt < 4; nt++) {
            int col = bn + wn + nt * 8 + tig * 2;
            float2 v0 = make_float2(acc[mt][nt][0], acc[mt][nt][1]);
            float2 v1 = make_float2(acc[mt][nt][2], acc[mt][nt][3]);
            if (EPI & EPI_BIAS) {
                float b0 = bias[col], b1 = bias[col + 1];
                v0.x += b0; v0.y += b1; v1.x += b0; v1.y += b1;
            }
            if (EPI & EPI_RESID) {
                const float* rp0 = resid + r0 * N + col;
                const float* rp1 = resid + r1 * N + col;
                v0.x += rp0[0]; v0.y += rp0[1];
                v1.x += rp1[0]; v1.y += rp1[1];
            }
            *(float2*)(C + r0 * N + col) = v0;
            *(float2*)(C + r1 * N + col) = v1;
        }
    }
}

// ---------------- double-LN core ----------------------------------------------
__device__ __forceinline__ void ln2_core(float4 v[4], int lane,
                                         const float* __restrict__ w1,
                                         const float* __restrict__ b1,
                                         const float* __restrict__ w2,
                                         const float* __restrict__ b2) {
    #pragma unroll
    for (int pass = 0; pass < 2; pass++) {
        const float* wz = pass ? w2 : w1;
        const float* bz = pass ? b2 : b1;
        float s = 0.f;
        #pragma unroll
        for (int i = 0; i < 4; i++) s += v[i].x + v[i].y + v[i].z + v[i].w;
        #pragma unroll
        for (int o = 16; o > 0; o >>= 1) s += __shfl_xor_sync(0xffffffffu, s, o);
        float mu = s * (1.f / DQ);
        float q = 0.f;
        #pragma unroll
        for (int i = 0; i < 4; i++) {
            float a = v[i].x - mu, b = v[i].y - mu, c = v[i].z - mu, d = v[i].w - mu;
            q += a * a + b * b + c * c + d * d;
        }
        #pragma unroll
        for (int o = 16; o > 0; o >>= 1) q += __shfl_xor_sync(0xffffffffu, q, o);
        float rs = rsqrtf(q * (1.f / DQ) + 1e-5f);
        #pragma unroll
        for (int i = 0; i < 4; i++) {
            float4 w = ((const float4*)wz)[lane + i * 32];
            float4 b = ((const float4*)bz)[lane + i * 32];
            v[i].x = (v[i].x - mu) * rs * w.x + b.x;
            v[i].y = (v[i].y - mu) * rs * w.y + b.y;
            v[i].z = (v[i].z - mu) * rs * w.z + b.z;
            v[i].w = (v[i].w - mu) * rs * w.w + b.w;
        }
    }
}

// ---------------- merged pre: weights->fp16 + xp_w pad + flags + ln2 ----------
#define W1N (2048*DQ/4)
#define W2N (DQ*DI/4)
#define W3N (DQ*4096/4)
#define W4N (64*DI/4)               // xp_w convert (16384)
#define W5N (64*DI/4)               // xp_w pad zero (16384)
#define WTOT (W1N + W2N + W3N + W4N + W5N)
#define WBLK ((WTOT + 255) / 256)
__global__ __launch_bounds__(256)
void pre_kernel(const float* __restrict__ s1, __half* __restrict__ h1,
                const float* __restrict__ s2, __half* __restrict__ h2,
                const float* __restrict__ s3, __half* __restrict__ h3,
                const float* __restrict__ s4, __half* __restrict__ h4,
                int* __restrict__ flags,
                const float* __restrict__ x,
                const float* __restrict__ w1, const float* __restrict__ b1,
                const float* __restrict__ w2, const float* __restrict__ b2,
                __half* __restrict__ oh) {
    if (blockIdx.x < WBLK) {
        int i = blockIdx.x * 256 + threadIdx.x;
        if (i < BQ * NCH * 64) flags[i] = 0;
        if (i >= WTOT) return;
        if (i >= W1N + W2N + W3N + W4N) {
            // zero-pad rows 64..127 of xp_w fp16
            int j = i - (W1N + W2N + W3N + W4N);
            *(uint2*)(h4 + 64 * DI + (size_t)j * 4) = make_uint2(0u, 0u);
            return;
        }
        const float* s; __half* h; int j;
        if (i < W1N)                  { s = s1; h = h1; j = i; }
        else if (i < W1N + W2N)       { s = s2; h = h2; j = i - W1N; }
        else if (i < W1N + W2N + W3N) { s = s3; h = h3; j = i - W1N - W2N; }
        else                          { s = s4; h = h4; j = i - W1N - W2N - W3N; }
        float4 v = ((const float4*)s)[j];
        __half2* hp = (__half2*)h;
        hp[2 * j + 0] = __halves2half2(__float2half_rn(v.x), __float2half_rn(v.y));
        hp[2 * j + 1] = __halves2half2(__float2half_rn(v.z), __float2half_rn(v.w));
        return;
    }
    int lane = threadIdx.x & 31;
    int row = (blockIdx.x - WBLK) * 8 + (threadIdx.x >> 5);
    const float4* xr = (const float4*)(x + (size_t)row * DQ);
    float4 v[4];
    #pragma unroll
    for (int i = 0; i < 4; i++) v[i] = xr[lane + i * 32];
    ln2_core(v, lane, w1, b1, w2, b2);
    __half2* hp = (__half2*)(oh + (size_t)row * DQ);
    #pragma unroll
    for (int i = 0; i < 4; i++) {
        int j = (lane + i * 32) * 2;
        hp[j + 0] = __halves2half2(__float2half_rn(v[i].x), __float2half_rn(v[i].y));
        hp[j + 1] = __halves2half2(__float2half_rn(v[i].z), __float2half_rn(v[i].w));
    }
}

// ---------------- fused ln2 + KAN basis (exp identity) -> fp16 ----------------
__global__ __launch_bounds__(256)
void ln2_basis_kernel(const float* __restrict__ x,
                      const float* __restrict__ w1, const float* __restrict__ b1,
                      const float* __restrict__ w2, const float* __restrict__ b2,
                      const float* __restrict__ grid,
                      __half* __restrict__ bh) {
    const float INV = 1.0f / 0.33f;
    int lane = threadIdx.x & 31;
    int row = blockIdx.x * 8 + (threadIdx.x >> 5);
    const float4* xr = (const float4*)(x + (size_t)row * DQ);
    float4 v[4];
    #pragma unroll
    for (int i = 0; i < 4; i++) v[i] = xr[lane + i * 32];
    ln2_core(v, lane, w1, b1, w2, b2);

    float cg[8];
    #pragma unroll
    for (int g = 0; g < 8; g++) cg[g] = __expf(2.f * __ldg(grid + g) * INV);

    __half* brow = bh + (size_t)row * 4096;
    #pragma unroll
    for (int i = 0; i < 4; i++) {
        float kv4[4] = {v[i].x, v[i].y, v[i].z, v[i].w};
        #pragma unroll
        for (int c = 0; c < 4; c++) {
            float kv = fminf(fmaxf(kv4[c], -14.f), 14.f);
            float E = __expf(-2.f * kv * INV);
            int d = (lane + i * 32) * 4 + c;
            __half hs[8];
            #pragma unroll
            for (int g = 0; g < 8; g++) {
                float e = E * cg[g];
                float op = 1.f + e;
                float val = (e > 1e30f) ? 0.f : __fdividef(4.f * e, op * op);
                hs[g] = __float2half_rn(val);
            }
            *(uint4*)(brow + d * 8) = *(uint4*)hs;
        }
    }
}

// ---------------- causal conv+silu, sliding-window, seg=8; fp32+fp16 out ------
__global__ __launch_bounds__(256)
void conv_silu_kernel(const float* __restrict__ xz,
                      const float* __restrict__ cw,
                      const float* __restrict__ cb,
                      float* __restrict__ xc,
                      __half* __restrict__ xch) {
    int b = blockIdx.x >> 8;
    int seg = blockIdx.x & 255;
    int d4 = threadIdx.x * 4;
    int t0 = seg * 8;
    size_t rbase = (size_t)b * LQ;

    float4 cw0 = *(const float4*)(cw + (d4 + 0) * 4);
    float4 cw1 = *(const float4*)(cw + (d4 + 1) * 4);
    float4 cw2 = *(const float4*)(cw + (d4 + 2) * 4);
    float4 cw3 = *(const float4*)(cw + (d4 + 3) * 4);
    float4 bias = *(const float4*)(cb + d4);

    float4 w0, w1, w2;
    {
        int t = t0 - 3;
        w0 = (t >= 0) ? *(const float4*)(xz + (rbase + t) * 2048 + d4)
                      : make_float4(0.f, 0.f, 0.f, 0.f);
        t = t0 - 2;
        w1 = (t >= 0) ? *(const float4*)(xz + (rbase + t) * 2048 + d4)
                      : make_float4(0.f, 0.f, 0.f, 0.f);
        t = t0 - 1;
        w2 = (t >= 0) ? *(const float4*)(xz + (rbase + t) * 2048 + d4)
                      : make_float4(0.f, 0.f, 0.f, 0.f);
    }
    #pragma unroll
    for (int tt = 0; tt < 8; tt++) {
        int t = t0 + tt;
        float4 cur = *(const float4*)(xz + (rbase + t) * 2048 + d4);
        float4 a = bias;
        a.x = fmaf(w0.x, cw0.x, fmaf(w1.x, cw0.y, fmaf(w2.x, cw0.z, fmaf(cur.x, cw0.w, a.x))));
        a.y = fmaf(w0.y, cw1.x, fmaf(w1.y, cw1.y, fmaf(w2.y, cw1.z, fmaf(cur.y, cw1.w, a.y))));
        a.z = fmaf(w0.z, cw2.x, fmaf(w1.z, cw2.y, fmaf(w2.z, cw2.z, fmaf(cur.z, cw2.w, a.z))));
        a.w = fmaf(w0.w, cw3.x, fmaf(w1.w, cw3.y, fmaf(w2.w, cw3.z, fmaf(cur.w, cw3.w, a.w))));
        a.x *= 1.f / (1.f + __expf(-a.x));
        a.y *= 1.f / (1.f + __expf(-a.y));
        a.z *= 1.f / (1.f + __expf(-a.z));
        a.w *= 1.f / (1.f + __expf(-a.w));
        *(float4*)(xc + (rbase + t) * DI + d4) = a;
        __half2 h0 = __halves2half2(__float2half_rn(a.x), __float2half_rn(a.y));
        __half2 h1 = __halves2half2(__float2half_rn(a.z), __float2half_rn(a.w));
        uint2 pk; pk.x = *(uint32_t*)&h0; pk.y = *(uint32_t*)&h1;
        *(uint2*)(xch + (rbase + t) * DI + d4) = pk;
        w0 = w1; w1 = w2; w2 = cur;
    }
}

// ---------------- single-pass chained scan (dbc stride 128) -------------------
#define S2_XV   0
#define S2_DBC  (TC*16)
#define S2_DL   (S2_DBC + TC*64)
#define S2_DTW  (S2_DL + TC*16)
#define S2_DTB  (S2_DTW + 32*16)
#define S2_END  (S2_DTB + 16)
#define S2_Y    S2_END
#define SCAN_SMEM ((S2_END + TC*16) * 4)     // 59456 B

__global__ __launch_bounds__(256)
void scan_kernel(const float* __restrict__ xc,
                 const float* __restrict__ dbc,
                 const float* __restrict__ dt_w, const float* __restrict__ dt_b,
                 const float* __restrict__ xz,
                 const float* __restrict__ A_log,
                 const float* __restrict__ D_param,
                 float* __restrict__ Si, int* __restrict__ flags,
                 __half* __restrict__ yh) {
    extern __shared__ float sm[];
    int bx = blockIdx.x;
    int dt = bx & 63;
    int c  = (bx >> 6) & 15;
    int b  = bx >> 10;
    int tid = threadIdx.x;
    int n = tid & 15, dloc = tid >> 4;
    int d = dt * 16 + dloc;
    size_t row0 = (size_t)b * LQ + c * TC;

    #pragma unroll
    for (int i = 0; i < 2; i++) {
        int idx = tid + i * 256;
        int t = idx >> 2, q = idx & 3;
        *(float4*)&sm[S2_XV + t * 16 + q * 4] =
            *(const float4*)(xc + (row0 + t) * DI + dt * 16 + q * 4);
    }
    #pragma unroll
    for (int i = 0; i < 8; i++) {
        int idx = tid + i * 256;
        int t = idx >> 4, q = idx & 15;
        *(float4*)&sm[S2_DBC + t * 64 + q * 4] =
            *(const float4*)(dbc + (row0 + t) * 128 + q * 4);
    }
    #pragma unroll
    for (int i = 0; i < 2; i++) {
        int idx = tid + i * 256;
        int d2 = idx >> 5, r = idx & 31;
        sm[S2_DTW + r * 16 + d2] = dt_w[(dt * 16 + d2) * 32 + r];
    }
    if (tid < 16) sm[S2_DTB + tid] = dt_b[dt * 16 + tid];
    __syncthreads();

    float dl8[8];
    #pragma unroll
    for (int i = 0; i < 8; i++) {
        int idx = tid + i * 256;
        int t = idx >> 4, d2 = idx & 15;
        float a = sm[S2_DTB + d2];
        #pragma unroll
        for (int r = 0; r < 32; r++)
            a = fmaf(sm[S2_DBC + t * 64 + r], sm[S2_DTW + r * 16 + d2], a);
        dl8[i] = (a > 20.f) ? a : log1pf(__expf(a));
    }
    __syncthreads();
    #pragma unroll
    for (int i = 0; i < 8; i++) {
        int idx = tid + i * 256;
        int t = idx >> 4, d2 = idx & 15;
        sm[S2_DL + t * 16 + d2] = dl8[i];
    }
    __syncthreads();

    float An = -__expf(A_log[d * DSTATE + n]);
    float Dp = D_param[d];

    float h = 0.f, P = 1.f;
    #pragma unroll 4
    for (int t = 0; t < TC; t++) {
        float dl = sm[S2_DL + t * 16 + dloc];
        float dA = __expf(dl * An);
        h = fmaf(dA, h, dl * sm[S2_DBC + t * 64 + 32 + n] * sm[S2_XV + t * 16 + dloc]);
        P *= dA;
    }

    size_t lane_o = (((size_t)b * NCH + c) * DI + (size_t)dt * 16) * DSTATE + tid;
    float Hin = 0.f;
    if (c > 0) {
        int fi = b * NCH * 64 + (c - 1) * 64 + dt;
        int f;
        do {
            f = *(volatile int*)&flags[fi];
            if (!f) __nanosleep(64);
        } while (!f);
        __threadfence();
        size_t po = (((size_t)b * NCH + (c - 1)) * DI + (size_t)dt * 16) * DSTATE + tid;
        Hin = *(volatile float*)&Si[po];
    }
    Si[lane_o] = fmaf(P, Hin, h);
    __threadfence();
    __syncthreads();
    if (tid == 0) {
        __threadfence();
        *(volatile int*)&flags[b * NCH * 64 + c * 64 + dt] = 1;
    }

    h = Hin;
    #pragma unroll 4
    for (int t = 0; t < TC; t++) {
        float dl = sm[S2_DL + t * 16 + dloc];
        float xv = sm[S2_XV + t * 16 + dloc];
        float dA = __expf(dl * An);
        h = fmaf(dA, h, dl * sm[S2_DBC + t * 64 + 32 + n] * xv);
        float p = h * sm[S2_DBC + t * 64 + 48 + n];
        p += __shfl_xor_sync(0xffffffffu, p, 1);
        p += __shfl_xor_sync(0xffffffffu, p, 2);
        p += __shfl_xor_sync(0xffffffffu, p, 4);
        p += __shfl_xor_sync(0xffffffffu, p, 8);
        if (n == 0) sm[S2_Y + t * 16 + dloc] = p + Dp * xv;
    }
    __syncthreads();

    #pragma unroll
    for (int i = 0; i < 8; i++) {
        int idx = tid + i * 256;
        int t = idx >> 4, dl2 = idx & 15;
        size_t row = row0 + t;
        float zv = xz[row * 2048 + DI + dt * 16 + dl2];
        float sz = zv / (1.f + __expf(-zv));
        yh[row * DI + dt * 16 + dl2] = __float2half_rn(sm[S2_Y + t * 16 + dl2] * sz);
    }
}

// ---------------- host orchestration ------------------------------------------
extern "C" void kernel_launch(void* const* d_in, const int* in_sizes, int n_in,
                              void* d_out, int out_size) {
    const float* x      = (const float*)d_in[0];
    const float* n1_w   = (const float*)d_in[1];
    const float* n1_b   = (const float*)d_in[2];
    const float* mn_w   = (const float*)d_in[3];
    const float* mn_b   = (const float*)d_in[4];
    const float* in_w   = (const float*)d_in[5];
    const float* in_b   = (const float*)d_in[6];
    const float* conv_w = (const float*)d_in[7];
    const float* conv_b = (const float*)d_in[8];
    const float* xp_w   = (const float*)d_in[9];
    const float* dt_w   = (const float*)d_in[10];
    const float* dt_b   = (const float*)d_in[11];
    const float* A_log  = (const float*)d_in[12];
    const float* D_par  = (const float*)d_in[13];
    const float* out_w  = (const float*)d_in[14];
    const float* out_b  = (const float*)d_in[15];
    const float* n2_w   = (const float*)d_in[16];
    const float* n2_b   = (const float*)d_in[17];
    const float* kn_w   = (const float*)d_in[18];
    const float* kn_b   = (const float*)d_in[19];
    const float* grid   = (const float*)d_in[20];
    const float* spl_w  = (const float*)d_in[21];
    float* out = (float*)d_out;

    float *p_xz, *p_xc, *p_dbc, *p_x2, *p_Si;
    int *p_flag;
    __half *p_uh, *p_iwh, *p_xch, *p_xpwh, *p_yh, *p_owh, *p_bh, *p_swh;
    cudaGetSymbolAddress((void**)&p_xz,   g_xz);
    cudaGetSymbolAddress((void**)&p_xc,   g_xc);
    cudaGetSymbolAddress((void**)&p_dbc,  g_dbc);
    cudaGetSymbolAddress((void**)&p_x2,   g_x2);
    cudaGetSymbolAddress((void**)&p_Si,   g_Si);
    cudaGetSymbolAddress((void**)&p_flag, g_flag);
    cudaGetSymbolAddress((void**)&p_uh,   g_uh);
    cudaGetSymbolAddress((void**)&p_iwh,  g_iwh);
    cudaGetSymbolAddress((void**)&p_xch,  g_xch);
    cudaGetSymbolAddress((void**)&p_xpwh, g_xpwh);
    cudaGetSymbolAddress((void**)&p_yh,   g_yh);
    cudaGetSymbolAddress((void**)&p_owh,  g_owh);
    cudaGetSymbolAddress((void**)&p_bh,   g_bh);
    cudaGetSymbolAddress((void**)&p_swh,  g_swh);

    cudaFuncSetAttribute(mgemm<EPI_BIAS>,
                         cudaFuncAttributeMaxDynamicSharedMemorySize, MG_SMEM);
    cudaFuncSetAttribute(mgemm<0>,
                         cudaFuncAttributeMaxDynamicSharedMemorySize, MG_SMEM);
    cudaFuncSetAttribute(mgemm<EPI_BIAS | EPI_RESID>,
                         cudaFuncAttributeMaxDynamicSharedMemorySize, MG_SMEM);
    cudaFuncSetAttribute(mgemm<EPI_RESID>,
                         cudaFuncAttributeMaxDynamicSharedMemorySize, MG_SMEM);
    cudaFuncSetAttribute(scan_kernel,
                         cudaFuncAttributeMaxDynamicSharedMemorySize, SCAN_SMEM);

    // 1. weights->fp16 (+ xp_w pad) + flags + u = LN(LN(x)) -> fp16
    pre_kernel<<<WBLK + BL / 8, 256>>>(
        in_w, p_iwh, out_w, p_owh, spl_w, p_swh, xp_w, p_xpwh, p_flag,
        x, n1_w, n1_b, mn_w, mn_b, p_uh);

    // 2. xz = u @ in_w^T + in_b   [4096 x 2048, K=512]
    mgemm<EPI_BIAS><<<dim3(2048 / 128, BL / 128), 256, MG_SMEM>>>(
        p_uh, p_iwh, in_b, nullptr, p_xz, 2048, DQ);

    // 3. xc = silu(conv(xm)) -> fp32 + fp16
    conv_silu_kernel<<<BQ * 256, 256>>>(p_xz, conv_w, conv_b, p_xc, p_xch);

    // 4. dbc = xc @ xp_w^T  [4096 x 128(pad), K=1024]  (tensor)
    mgemm<0><<<dim3(1, BL / 128), 256, MG_SMEM>>>(
        p_xch, p_xpwh, nullptr, nullptr, p_dbc, 128, DI);

    // 5. single-pass chained scan (dt_proj fused) -> y fp16
    scan_kernel<<<BQ * NCH * 64, 256, SCAN_SMEM>>>(
        p_xc, p_dbc, dt_w, dt_b, p_xz, A_log, D_par, p_Si, p_flag, p_yh);

    // 6. x2 = x + y @ out_w^T + out_b  [4096 x 512, K=1024]
    mgemm<EPI_BIAS | EPI_RESID><<<dim3(DQ / 128, BL / 128), 256, MG_SMEM>>>(
        p_yh, p_owh, out_b, x, p_x2, DQ, DI);

    // 7. basis = sech2 of LN(LN(x2)) -> fp16 (exp identity)
    ln2_basis_kernel<<<BL / 8, 256>>>(p_x2, n2_w, n2_b, kn_w, kn_b, grid, p_bh);

    // 8. out = x2 + basis @ spl_w^T  [4096 x 512, K=4096]
    mgemm<EPI_RESID><<<dim3(DQ / 128, BL / 128), 256, MG_SMEM>>>(
        p_bh, p_swh, nullptr, p_x2, out, DQ, 4096);

    (void)in_sizes; (void)n_in; (void)out_size;
}